// round 1
// baseline (speedup 1.0000x reference)
#include <cuda_runtime.h>
#include <cuda_bf16.h>

// ---------------- problem constants (from reference setup_inputs) ----------------
constexpr int B = 64;
constexpr int P = 24576;
constexpr int C = 81;            // NUM_CLASSES + 1
constexpr int NEG_POS_RATIO = 3;

constexpr int WARPS_PER_BLOCK = 8;
constexpr int APW = 16;                                // anchors per warp
constexpr int ANCHORS_PER_BLOCK = WARPS_PER_BLOCK * APW; // 128
constexpr int NBLOCKS1 = (B * P) / ANCHORS_PER_BLOCK;    // 12288
constexpr int BLOCKS_PER_IMAGE = P / ANCHORS_PER_BLOCK;  // 192

// ---------------- scratch (device globals; no allocation allowed) ----------------
__device__ float g_ce_neg[B * P];      // CE for negatives, 0 for positives
__device__ int   g_num_pos[B];
__device__ float g_partials[NBLOCKS1]; // per-block (pos CE + huber) partial sums
__device__ float g_neg_sum[B];

// ---------------- helpers ----------------
__device__ __forceinline__ float huber1(float d) {
    float ad = fabsf(d);
    return ad < 1.0f ? 0.5f * d * d : ad - 0.5f;
}

// ---------------- kernel 0: init ----------------
__global__ void k_init() {
    int i = threadIdx.x;
    if (i < B) g_num_pos[i] = 0;
}

// ---------------- kernel 1: per-anchor CE + huber ----------------
__global__ void __launch_bounds__(256) k_ce(
    const float* __restrict__ loc_preds,
    const float* __restrict__ cls_preds,
    const float* __restrict__ loc_targets,
    const int*   __restrict__ cls_targets)
{
    const int lane = threadIdx.x & 31;
    const int warp = threadIdx.x >> 5;
    const long base = (long)blockIdx.x * ANCHORS_PER_BLOCK;

    float acc = 0.0f;   // lane 0 accumulates pos CE + huber
    int poscnt = 0;     // lane 0 counts positives

    #pragma unroll 4
    for (int i = 0; i < APW; i++) {
        const long a = base + (long)i * WARPS_PER_BLOCK + warp;
        const float* row = cls_preds + a * C;

        float x0 = row[lane];
        float x1 = row[lane + 32];
        float x2 = (lane < C - 64) ? row[lane + 64] : -1e30f;
        int t = cls_targets[a];   // uniform within warp

        // warp max
        float m = fmaxf(x0, fmaxf(x1, x2));
        #pragma unroll
        for (int o = 16; o; o >>= 1) m = fmaxf(m, __shfl_xor_sync(0xFFFFFFFFu, m, o));

        // warp sum of exp
        float s = __expf(x0 - m) + __expf(x1 - m);
        if (lane < C - 64) s += __expf(x2 - m);
        #pragma unroll
        for (int o = 16; o; o >>= 1) s += __shfl_xor_sync(0xFFFFFFFFu, s, o);

        // fetch target logit via shuffle from its owner lane
        float cand = (t < 32) ? x0 : ((t < 64) ? x1 : x2);
        float xt = __shfl_sync(0xFFFFFFFFu, cand, t & 31);

        float ce = __logf(s) + m - xt;
        bool pos = (t > 0);

        if (lane == 0) {
            g_ce_neg[a] = pos ? 0.0f : ce;
            if (pos) {
                float4 p = reinterpret_cast<const float4*>(loc_preds)[a];
                float4 q = reinterpret_cast<const float4*>(loc_targets)[a];
                float h = huber1(p.x - q.x) + huber1(p.y - q.y) +
                          huber1(p.z - q.z) + huber1(p.w - q.w);
                acc += ce + h;
                poscnt++;
            }
        }
    }

    __shared__ float sacc[WARPS_PER_BLOCK];
    __shared__ int   scnt[WARPS_PER_BLOCK];
    if (lane == 0) { sacc[warp] = acc; scnt[warp] = poscnt; }
    __syncthreads();
    if (threadIdx.x == 0) {
        float tot = 0.0f; int c = 0;
        #pragma unroll
        for (int w = 0; w < WARPS_PER_BLOCK; w++) { tot += sacc[w]; c += scnt[w]; }
        g_partials[blockIdx.x] = tot;
        atomicAdd(&g_num_pos[blockIdx.x / BLOCKS_PER_IMAGE], c);  // exact int -> deterministic
    }
}

// ---------------- kernel 2: per-image hard-negative sum ----------------
// Fast path: if k >= neg_count, the top-k IS all negatives -> full row sum
// (positives are stored as 0). General path: exact top-k via threshold
// binary search on float bits (values >= 0), tie-corrected:
//   sum_topk = sum(v > t) + (k - count(v > t)) * t,  t = k-th largest value.
__global__ void __launch_bounds__(256) k_neg() {
    const int b = blockIdx.x;
    const int tid = threadIdx.x;
    const float* row = g_ce_neg + (size_t)b * P;

    const int np = g_num_pos[b];
    const long negc = (long)P - np;
    const long k = min((long)NEG_POS_RATIO * (long)np, negc);

    __shared__ float sf[256];
    __shared__ int   si[256];
    __shared__ unsigned s_bits;

    // full deterministic row sum
    float s = 0.0f;
    for (int i = tid; i < P; i += 256) s += row[i];
    sf[tid] = s; __syncthreads();
    for (int o = 128; o; o >>= 1) { if (tid < o) sf[tid] += sf[tid + o]; __syncthreads(); }
    float full = sf[0];
    __syncthreads();

    float result;
    if (k >= negc) {
        result = full;
    } else if (k <= 0) {
        result = 0.0f;
    } else {
        // max value
        float m = 0.0f;
        for (int i = tid; i < P; i += 256) m = fmaxf(m, row[i]);
        sf[tid] = m; __syncthreads();
        for (int o = 128; o; o >>= 1) { if (tid < o) sf[tid] = fmaxf(sf[tid], sf[tid + o]); __syncthreads(); }
        m = sf[0];
        __syncthreads();

        unsigned lo = 0u, hi = __float_as_uint(fmaxf(m, 0.0f));
        while (lo < hi) {
            unsigned mid = lo + ((hi - lo + 1u) >> 1);
            float thr = __uint_as_float(mid);
            int c = 0;
            for (int i = tid; i < P; i += 256) c += (row[i] >= thr);
            si[tid] = c; __syncthreads();
            for (int o = 128; o; o >>= 1) { if (tid < o) si[tid] += si[tid + o]; __syncthreads(); }
            int cge = si[0];
            __syncthreads();
            if ((long)cge >= k) lo = mid; else hi = mid - 1u;
        }
        if (tid == 0) s_bits = lo;
        __syncthreads();
        float thr = __uint_as_float(s_bits);

        float sg = 0.0f; int cg = 0;
        for (int i = tid; i < P; i += 256) {
            float v = row[i];
            if (v > thr) { sg += v; cg++; }
        }
        sf[tid] = sg; si[tid] = cg; __syncthreads();
        for (int o = 128; o; o >>= 1) {
            if (tid < o) { sf[tid] += sf[tid + o]; si[tid] += si[tid + o]; }
            __syncthreads();
        }
        result = sf[0] + (float)(k - (long)si[0]) * thr;
    }

    if (tid == 0) g_neg_sum[b] = result;
}

// ---------------- kernel 3: final reduction ----------------
__global__ void __launch_bounds__(256) k_final(float* __restrict__ out) {
    const int tid = threadIdx.x;
    __shared__ float sf[256];

    float s = 0.0f;
    for (int i = tid; i < NBLOCKS1; i += 256) s += g_partials[i];
    sf[tid] = s; __syncthreads();
    for (int o = 128; o; o >>= 1) { if (tid < o) sf[tid] += sf[tid + o]; __syncthreads(); }

    if (tid == 0) {
        float total = sf[0];
        long sumpos = 0;
        for (int b = 0; b < B; b++) { total += g_neg_sum[b]; sumpos += g_num_pos[b]; }
        float N = (float)(sumpos > 0 ? sumpos : 1);
        out[0] = total / N;
    }
}

// ---------------- launch ----------------
extern "C" void kernel_launch(void* const* d_in, const int* in_sizes, int n_in,
                              void* d_out, int out_size) {
    const float* loc_preds   = (const float*)d_in[0];
    const float* cls_preds   = (const float*)d_in[1];
    const float* loc_targets = (const float*)d_in[2];
    const int*   cls_targets = (const int*)d_in[3];
    float* out = (float*)d_out;

    k_init<<<1, 64>>>();
    k_ce<<<NBLOCKS1, 256>>>(loc_preds, cls_preds, loc_targets, cls_targets);
    k_neg<<<B, 256>>>();
    k_final<<<1, 256>>>(out);
}

// round 3
// speedup vs baseline: 2.1431x; 2.1431x over previous
#include <cuda_runtime.h>
#include <cuda_bf16.h>

// ---------------- problem constants (from reference setup_inputs) ----------------
constexpr int B = 64;
constexpr int P = 24576;
constexpr int C = 81;            // NUM_CLASSES + 1
constexpr int NEG_POS_RATIO = 3;

constexpr int TPB = 128;                       // threads per block (k_ce)
constexpr int APB = 128;                       // anchors per block = TPB (thread-per-anchor)
constexpr int NBLOCKS1 = (B * P) / APB;        // 12288
constexpr int BLOCKS_PER_IMAGE = P / APB;      // 192
constexpr int TILE_F4 = APB * C / 4;           // 2592 float4 per cls tile

// ---------------- scratch (device globals; no allocation allowed) ----------------
__device__ float g_ce_neg[B * P];      // CE for negatives, 0 for positives
__device__ int   g_num_pos[B];
__device__ float g_partials[NBLOCKS1]; // per-block (pos CE + huber) partial sums
__device__ float g_neg_sum[B];

// ---------------- helpers ----------------
__device__ __forceinline__ float huber1(float d) {
    float ad = fabsf(d);
    return ad < 1.0f ? 0.5f * d * d : ad - 0.5f;
}

// ---------------- kernel 0: init ----------------
__global__ void k_init() {
    int i = threadIdx.x;
    if (i < B) g_num_pos[i] = 0;
}

// ---------------- kernel 1: per-anchor CE + huber (thread-per-anchor, smem-staged) ----
__global__ void __launch_bounds__(TPB) k_ce(
    const float* __restrict__ loc_preds,
    const float* __restrict__ cls_preds,
    const float* __restrict__ loc_targets,
    const int*   __restrict__ cls_targets)
{
    __shared__ float s_cls[APB * C];           // 41472 B; anchor-major, verbatim copy
    __shared__ float sred[TPB];
    __shared__ int   scnt[TPB];

    const int tid = threadIdx.x;
    const long base = (long)blockIdx.x * APB;

    // ---- stage cls tile: coalesced float4 loads (block tile is 16B aligned) ----
    const float4* __restrict__ src = reinterpret_cast<const float4*>(cls_preds + base * C);
    float4* dst = reinterpret_cast<float4*>(s_cls);
    #pragma unroll 7
    for (int idx = tid; idx < TILE_F4; idx += TPB)
        dst[idx] = src[idx];

    // prefetch per-anchor scalars while smem fills
    const long a = base + tid;
    const int t = cls_targets[a];
    float4 lp = reinterpret_cast<const float4*>(loc_preds)[a];
    float4 lt = reinterpret_cast<const float4*>(loc_targets)[a];

    __syncthreads();

    // ---- per-thread softmax CE over 81 classes (stride-81 LDS: conflict-free) ----
    const float* __restrict__ row = s_cls + tid * C;

    float m = row[0];
    #pragma unroll
    for (int c = 1; c < C; c++) m = fmaxf(m, row[c]);

    float s = 0.0f;
    #pragma unroll
    for (int c = 0; c < C; c++) s += __expf(row[c] - m);

    const float ce = __logf(s) + m - row[t];
    const bool pos = (t > 0);

    g_ce_neg[a] = pos ? 0.0f : ce;

    float acc = 0.0f;
    if (pos) {
        acc = ce + huber1(lp.x - lt.x) + huber1(lp.y - lt.y) +
                   huber1(lp.z - lt.z) + huber1(lp.w - lt.w);
    }

    // ---- deterministic block reduction ----
    sred[tid] = acc;
    scnt[tid] = pos ? 1 : 0;
    __syncthreads();
    #pragma unroll
    for (int o = TPB / 2; o > 0; o >>= 1) {
        if (tid < o) { sred[tid] += sred[tid + o]; scnt[tid] += scnt[tid + o]; }
        __syncthreads();
    }
    if (tid == 0) {
        g_partials[blockIdx.x] = sred[0];
        atomicAdd(&g_num_pos[blockIdx.x / BLOCKS_PER_IMAGE], scnt[0]);  // exact int -> deterministic
    }
}

// ---------------- kernel 2: per-image hard-negative sum ----------------
// Fast path (taken on this data): k >= neg_count -> full row sum (positives are 0).
// General path: exact tie-corrected top-k via threshold binary search on float bits.
__global__ void __launch_bounds__(256) k_neg() {
    const int b = blockIdx.x;
    const int tid = threadIdx.x;
    const float* row = g_ce_neg + (size_t)b * P;

    const int np = g_num_pos[b];
    const long negc = (long)P - np;
    const long k = min((long)NEG_POS_RATIO * (long)np, negc);

    __shared__ float sf[256];
    __shared__ int   si[256];
    __shared__ unsigned s_bits;

    // full deterministic row sum (vectorized)
    const float4* row4 = reinterpret_cast<const float4*>(row);
    float s = 0.0f;
    for (int i = tid; i < P / 4; i += 256) {
        float4 v = row4[i];
        s += (v.x + v.y) + (v.z + v.w);
    }
    sf[tid] = s; __syncthreads();
    for (int o = 128; o; o >>= 1) { if (tid < o) sf[tid] += sf[tid + o]; __syncthreads(); }
    float full = sf[0];
    __syncthreads();

    float result;
    if (k >= negc) {
        result = full;
    } else if (k <= 0) {
        result = 0.0f;
    } else {
        // max value
        float m = 0.0f;
        for (int i = tid; i < P; i += 256) m = fmaxf(m, row[i]);
        sf[tid] = m; __syncthreads();
        for (int o = 128; o; o >>= 1) { if (tid < o) sf[tid] = fmaxf(sf[tid], sf[tid + o]); __syncthreads(); }
        m = sf[0];
        __syncthreads();

        unsigned lo = 0u, hi = __float_as_uint(fmaxf(m, 0.0f));
        while (lo < hi) {
            unsigned mid = lo + ((hi - lo + 1u) >> 1);
            float thr = __uint_as_float(mid);
            int c = 0;
            for (int i = tid; i < P; i += 256) c += (row[i] >= thr);
            si[tid] = c; __syncthreads();
            for (int o = 128; o; o >>= 1) { if (tid < o) si[tid] += si[tid + o]; __syncthreads(); }
            int cge = si[0];
            __syncthreads();
            if ((long)cge >= k) lo = mid; else hi = mid - 1u;
        }
        if (tid == 0) s_bits = lo;
        __syncthreads();
        float thr = __uint_as_float(s_bits);

        float sg = 0.0f; int cg = 0;
        for (int i = tid; i < P; i += 256) {
            float v = row[i];
            if (v > thr) { sg += v; cg++; }
        }
        sf[tid] = sg; si[tid] = cg; __syncthreads();
        for (int o = 128; o; o >>= 1) {
            if (tid < o) { sf[tid] += sf[tid + o]; si[tid] += si[tid + o]; }
            __syncthreads();
        }
        result = sf[0] + (float)(k - (long)si[0]) * thr;
    }

    if (tid == 0) g_neg_sum[b] = result;
}

// ---------------- kernel 3: final reduction ----------------
__global__ void __launch_bounds__(1024) k_final(float* __restrict__ out) {
    const int tid = threadIdx.x;
    __shared__ float sf[1024];
    __shared__ int   si[1024];

    float s = 0.0f;
    for (int i = tid; i < NBLOCKS1; i += 1024) s += g_partials[i];
    int c = 0;
    if (tid < B) { s += g_neg_sum[tid]; c = g_num_pos[tid]; }

    sf[tid] = s; si[tid] = c; __syncthreads();
    for (int o = 512; o; o >>= 1) {
        if (tid < o) { sf[tid] += sf[tid + o]; si[tid] += si[tid + o]; }
        __syncthreads();
    }
    if (tid == 0) {
        float N = (float)(si[0] > 0 ? si[0] : 1);
        out[0] = sf[0] / N;
    }
}

// ---------------- launch ----------------
extern "C" void kernel_launch(void* const* d_in, const int* in_sizes, int n_in,
                              void* d_out, int out_size) {
    const float* loc_preds   = (const float*)d_in[0];
    const float* cls_preds   = (const float*)d_in[1];
    const float* loc_targets = (const float*)d_in[2];
    const int*   cls_targets = (const int*)d_in[3];
    float* out = (float*)d_out;

    k_init<<<1, 64>>>();
    k_ce<<<NBLOCKS1, TPB>>>(loc_preds, cls_preds, loc_targets, cls_targets);
    k_neg<<<B, 256>>>();
    k_final<<<1, 1024>>>(out);
}